// round 14
// baseline (speedup 1.0000x reference)
#include <cuda_runtime.h>

// QuantumLayer via Pauli-transfer closed form — single fused persistent kernel.
//
// o_j = sum over the 41 even-Y Pauli strings t in {I,X,Y}^4 of
//       W_j[t] * prod_w (1 | cos th_w | sin th_w).
//
// Prologue (ONCE per block, single wave): each warp simulates the fixed real
// orthogonal operator U (params-only) with lane (l&15) holding column (l&15)
// in registers, then computes its 5-6 weight quadruples via warp shuffles.
// String descriptors (f, ymask, sign) are precomputed __constant__ packed
// words — no global loads, no integer division, unrolled for SHFL ILP.
//
// Main body: grid-stride loop, 4 batch items per thread as two f32x2
// lane-pairs; weight pairs packed as ulonglong2 -> 2x LDS.128 per term.

typedef unsigned long long ull;

__device__ __forceinline__ ull pk(float a, float b) {
    ull r; asm("mov.b64 %0, {%1, %2};" : "=l"(r) : "f"(a), "f"(b)); return r;
}
__device__ __forceinline__ void upk(ull v, float& a, float& b) {
    asm("mov.b64 {%0, %1}, %2;" : "=f"(a), "=f"(b) : "l"(v));
}
__device__ __forceinline__ ull f2mul(ull a, ull b) {
    ull r; asm("mul.rn.f32x2 %0, %1, %2;" : "=l"(r) : "l"(a), "l"(b)); return r;
}
__device__ __forceinline__ ull f2fma(ull a, ull b, ull c) {
    ull r; asm("fma.rn.f32x2 %0, %1, %2, %3;" : "=l"(r) : "l"(a), "l"(b), "l"(c)); return r;
}

#define F2_ONE 0x3F8000003F800000ULL   // (1.0f, 1.0f)

// Packed descriptors for the 41 even-Y Pauli strings, ascending enc order
// (== main loop idx order, validated in R10):
//   bits [0:4)  f     = XOR flip mask (bit3 = wire0)
//   bits [4:8)  ymask = wires with Y
//   bit  [8]    neg   = 1 iff nY == 2  (sign = -1; nY in {0,4} -> +1)
__constant__ unsigned short DESC41[41] = {
    0x000, 0x001, 0x002, 0x003, 0x133, 0x004, 0x005, 0x006, 0x007, 0x137,
    0x155, 0x157, 0x166, 0x167, 0x008, 0x009, 0x00A, 0x00B, 0x13B, 0x00C,
    0x00D, 0x00E, 0x00F, 0x13F, 0x15D, 0x15F, 0x16E, 0x16F, 0x199, 0x19B,
    0x1AA, 0x1AB, 0x19D, 0x19F, 0x1AE, 0x1AF, 0x1CC, 0x1CD, 0x1CE, 0x1CF,
    0x0FF
};

#define CNOTF(c_, t_)                                                         \
    {                                                                         \
        const int mc = 8 >> (c_), mt = 8 >> (t_);                             \
        _Pragma("unroll")                                                     \
        for (int k = 0; k < 16; ++k)                                          \
            if ((k & mc) && !(k & mt)) {                                      \
                float tmp = st[k]; st[k] = st[k | mt]; st[k | mt] = tmp;      \
            }                                                                 \
    }

#define SINCOS2(dc, ds, xa, xb)                                               \
    { float sa_, ca_, sb_, cb_;                                               \
      __sincosf(xa, &sa_, &ca_); __sincosf(xb, &sb_, &cb_);                   \
      dc = pk(ca_, cb_); ds = pk(sa_, sb_); }

__global__ void __launch_bounds__(256, 3)
quantum_layer_kernel(const float4* __restrict__ inp,
                     const float*  __restrict__ params,
                     float4* __restrict__ out, int nquad, int B)
{
    __shared__ ulonglong2 sWA[41];   // packed {W0, W1} per term
    __shared__ ulonglong2 sWB[41];   // packed {W2, W3} per term

    const int tid  = threadIdx.x;
    const int wid  = tid >> 5;
    const int lane = tid & 31;

    // ================= Prologue: weights via register-resident U + shuffles.
    {
        float pc[8], ps[8];
#pragma unroll
        for (int g = 0; g < 8; ++g)
            __sincosf(0.5f * __ldg(&params[g]), &ps[g], &pc[g]);

        const int col = lane & 15;       // lane (l&15) holds U column (l&15)
        float st[16];
#pragma unroll
        for (int i = 0; i < 16; ++i) st[i] = (i == col) ? 1.0f : 0.0f;

        CNOTF(0, 1); CNOTF(1, 2); CNOTF(2, 3);
#pragma unroll
        for (int layer = 0; layer < 2; ++layer) {
#pragma unroll
            for (int w = 0; w < 4; ++w) {
                const float c = pc[layer * 4 + w], s = ps[layer * 4 + w];
                const int m = 8 >> w;
#pragma unroll
                for (int k = 0; k < 16; ++k)
                    if (!(k & m)) {
                        const int k1 = k | m;
                        float a0 = st[k], a1 = st[k1];
                        st[k]  = c * a0 - s * a1;
                        st[k1] = s * a0 + c * a1;
                    }
            }
            CNOTF(0, 1); CNOTF(1, 2); CNOTF(2, 3); CNOTF(3, 0);
        }

        // Warp wid handles tIdx = wid + 8*k, k = 0..5 (41 strings total).
#pragma unroll 3
        for (int k = 0; k < 6; ++k) {
            const int tIdx = wid + 8 * k;
            if (tIdx < 41) {
                const int desc  = DESC41[tIdx];
                const int f     = desc & 15;
                const int ymask = (desc >> 4) & 15;
                const float sgn = (desc & 0x100) ? -0.0625f : 0.0625f;

                // prod[m] = U[m, l] * U[m, l^f]  (f < 16: stays in half-warp)
                float prod[16];
#pragma unroll
                for (int m = 0; m < 16; ++m) {
                    float o = __shfl_xor_sync(0xffffffffu, st[m], f);
                    prod[m] = st[m] * o;
                }

                // S_j = sum_m prod[m] * (1 - 2*bit_{3-j}(m)) via butterflies
                float u[8], v[8];
#pragma unroll
                for (int a = 0; a < 8; ++a) {
                    u[a] = prod[2 * a] + prod[2 * a + 1];
                    v[a] = prod[2 * a] - prod[2 * a + 1];
                }
                float S3 = ((v[0] + v[1]) + (v[2] + v[3])) +
                           ((v[4] + v[5]) + (v[6] + v[7]));
                float a2[4], b2[4];
#pragma unroll
                for (int b = 0; b < 4; ++b) {
                    a2[b] = u[2 * b] + u[2 * b + 1];
                    b2[b] = u[2 * b] - u[2 * b + 1];
                }
                float S2 = (b2[0] + b2[1]) + (b2[2] + b2[3]);
                float A0 = a2[0] + a2[1], B0 = a2[0] - a2[1];
                float A1 = a2[2] + a2[3], B1 = a2[2] - a2[3];
                float S1 = B0 + B1;
                float S0 = A0 - A1;

                // v(l) parity sign, folded with sign/16.
                const float scale = (__popc(col & ymask) & 1) ? -sgn : sgn;
                float w0 = S0 * scale, w1 = S1 * scale;
                float w2 = S2 * scale, w3 = S3 * scale;

                // Sum over the 16 columns (xor offsets within half-warp).
#pragma unroll
                for (int off = 1; off < 16; off <<= 1) {
                    w0 += __shfl_xor_sync(0xffffffffu, w0, off);
                    w1 += __shfl_xor_sync(0xffffffffu, w1, off);
                    w2 += __shfl_xor_sync(0xffffffffu, w2, off);
                    w3 += __shfl_xor_sync(0xffffffffu, w3, off);
                }
                if (lane == 0) {
                    sWA[tIdx] = make_ulonglong2(pk(w0, w0), pk(w1, w1));
                    sWB[tIdx] = make_ulonglong2(pk(w2, w2), pk(w3, w3));
                }
            }
        }
    }
    __syncthreads();

    // ================= Main body: grid-stride, 4 items/thread (pairs P, Q).
    const int stride = gridDim.x * blockDim.x;
    for (int t = blockIdx.x * blockDim.x + tid; t < nquad; t += stride) {
        const int i0 = 4 * t;
        const bool hB = (i0 + 1) < B, hC = (i0 + 2) < B, hD = (i0 + 3) < B;
        float4 inA = inp[i0];
        float4 inB = hB ? inp[i0 + 1] : inA;
        float4 inC = hC ? inp[i0 + 2] : inA;
        float4 inD = hD ? inp[i0 + 3] : inA;

        ull CP[4], SP[4], CQ[4], SQ[4];
        SINCOS2(CP[0], SP[0], inA.x, inB.x); SINCOS2(CQ[0], SQ[0], inC.x, inD.x);
        SINCOS2(CP[1], SP[1], inA.y, inB.y); SINCOS2(CQ[1], SQ[1], inC.y, inD.y);
        SINCOS2(CP[2], SP[2], inA.z, inB.z); SINCOS2(CQ[2], SQ[2], inC.z, inD.z);
        SINCOS2(CP[3], SP[3], inA.w, inB.w); SINCOS2(CQ[3], SQ[3], inC.w, inD.w);

        // Monomials over wires 0,1 for each lane-pair.
        ull mP01[9], mQ01[9];
        mP01[0] = F2_ONE;               mQ01[0] = F2_ONE;
        mP01[1] = CP[1];                mQ01[1] = CQ[1];
        mP01[2] = SP[1];                mQ01[2] = SQ[1];
        mP01[3] = CP[0];                mQ01[3] = CQ[0];
        mP01[6] = SP[0];                mQ01[6] = SQ[0];
        mP01[4] = f2mul(CP[0], CP[1]);  mQ01[4] = f2mul(CQ[0], CQ[1]);
        mP01[5] = f2mul(CP[0], SP[1]);  mQ01[5] = f2mul(CQ[0], SQ[1]);
        mP01[7] = f2mul(SP[0], CP[1]);  mQ01[7] = f2mul(SQ[0], CQ[1]);
        mP01[8] = f2mul(SP[0], SP[1]);  mQ01[8] = f2mul(SQ[0], SQ[1]);

        ull oP0 = 0, oP1 = 0, oP2 = 0, oP3 = 0;
        ull oQ0 = 0, oQ1 = 0, oQ2 = 0, oQ3 = 0;
        int idx = 0;
#pragma unroll
        for (int t0 = 0; t0 < 3; ++t0)
#pragma unroll
        for (int t1 = 0; t1 < 3; ++t1) {
            const int p01 = t0 * 3 + t1;
#pragma unroll
            for (int t2 = 0; t2 < 3; ++t2) {
                ull preP, preQ;
                bool preOne = false;
                if (t2 == 0) {
                    preP = mP01[p01]; preQ = mQ01[p01]; preOne = (p01 == 0);
                } else if (p01 == 0) {
                    preP = (t2 == 1) ? CP[2] : SP[2];
                    preQ = (t2 == 1) ? CQ[2] : SQ[2];
                } else {
                    preP = f2mul(mP01[p01], (t2 == 1) ? CP[2] : SP[2]);
                    preQ = f2mul(mQ01[p01], (t2 == 1) ? CQ[2] : SQ[2]);
                }
#pragma unroll
                for (int t3 = 0; t3 < 3; ++t3) {
                    const int ny = (t0 == 2) + (t1 == 2) + (t2 == 2) + (t3 == 2);
                    if (ny & 1) continue;   // odd-Y strings have zero weight
                    ull mP, mQ;
                    if (t3 == 0) {
                        mP = preP; mQ = preQ;
                    } else if (preOne) {
                        mP = (t3 == 1) ? CP[3] : SP[3];
                        mQ = (t3 == 1) ? CQ[3] : SQ[3];
                    } else {
                        mP = f2mul(preP, (t3 == 1) ? CP[3] : SP[3]);
                        mQ = f2mul(preQ, (t3 == 1) ? CQ[3] : SQ[3]);
                    }
                    // 2x LDS.128 per term, reused by both lane-pairs.
                    ulonglong2 wA = sWA[idx];   // {W0, W1}
                    ulonglong2 wB = sWB[idx];   // {W2, W3}
                    oP0 = f2fma(mP, wA.x, oP0);  oQ0 = f2fma(mQ, wA.x, oQ0);
                    oP1 = f2fma(mP, wA.y, oP1);  oQ1 = f2fma(mQ, wA.y, oQ1);
                    oP2 = f2fma(mP, wB.x, oP2);  oQ2 = f2fma(mQ, wB.x, oQ2);
                    oP3 = f2fma(mP, wB.y, oP3);  oQ3 = f2fma(mQ, wB.y, oQ3);
                    ++idx;
                }
            }
        }

        float a0, b0, a1, b1, a2, b2, a3, b3;
        upk(oP0, a0, b0); upk(oP1, a1, b1); upk(oP2, a2, b2); upk(oP3, a3, b3);
        out[i0] = make_float4(a0, a1, a2, a3);
        if (hB) out[i0 + 1] = make_float4(b0, b1, b2, b3);
        upk(oQ0, a0, b0); upk(oQ1, a1, b1); upk(oQ2, a2, b2); upk(oQ3, a3, b3);
        if (hC) out[i0 + 2] = make_float4(a0, a1, a2, a3);
        if (hD) out[i0 + 3] = make_float4(b0, b1, b2, b3);
    }
}

extern "C" void kernel_launch(void* const* d_in, const int* in_sizes, int n_in,
                              void* d_out, int out_size)
{
    const float* inputs = (const float*)d_in[0];   // (B, 4) float32
    const float* params = (const float*)d_in[1];   // (2, 4) float32
    float* outp = (float*)d_out;                   // (B, 4) float32

    int B = in_sizes[0] / 4;
    int nquad = (B + 3) / 4;
    int threads = 256;
    // Persistent single-wave grid: 152 SMs x 3 blocks/SM (launch_bounds cap).
    int blocks = 456;
    int needed = (nquad + threads - 1) / threads;
    if (blocks > needed) blocks = needed;

    quantum_layer_kernel<<<blocks, threads>>>((const float4*)inputs, params,
                                              (float4*)outp, nquad, B);
}

// round 16
// speedup vs baseline: 1.5283x; 1.5283x over previous
#include <cuda_runtime.h>

// QuantumLayer via Pauli-transfer closed form — single fused kernel.
//
// o_j = sum over the 41 even-Y Pauli strings t in {I,X,Y}^4 of
//       W_j[t] * prod_w (1 | cos th_w | sin th_w).
//
// Prologue (per block): each warp simulates the fixed real orthogonal
// operator U (params-only) with lane (l&15) holding column (l&15) in
// registers, then computes its 5-6 weight quadruples via warp shuffles.
// String descriptors (f, ymask, sign) come from a __constant__ packed table
// (validated R13) — no global loads, no int division, unrolled for SHFL ILP.
//
// Main body: one tile per block (R13's persistent grid-stride regressed the
// memory system 2.5x — block-ordered streaming wins here), 4 batch items
// per thread as two f32x2 lane-pairs; weight pairs packed as ulonglong2 ->
// 2x LDS.128 broadcast per term.

typedef unsigned long long ull;

__device__ __forceinline__ ull pk(float a, float b) {
    ull r; asm("mov.b64 %0, {%1, %2};" : "=l"(r) : "f"(a), "f"(b)); return r;
}
__device__ __forceinline__ void upk(ull v, float& a, float& b) {
    asm("mov.b64 {%0, %1}, %2;" : "=f"(a), "=f"(b) : "l"(v));
}
__device__ __forceinline__ ull f2mul(ull a, ull b) {
    ull r; asm("mul.rn.f32x2 %0, %1, %2;" : "=l"(r) : "l"(a), "l"(b)); return r;
}
__device__ __forceinline__ ull f2fma(ull a, ull b, ull c) {
    ull r; asm("fma.rn.f32x2 %0, %1, %2, %3;" : "=l"(r) : "l"(a), "l"(b), "l"(c)); return r;
}

#define F2_ONE 0x3F8000003F800000ULL   // (1.0f, 1.0f)

// Packed descriptors for the 41 even-Y Pauli strings, ascending enc order
// (== main loop idx order). Validated in R13 (rel_err 7.3e-6):
//   bits [0:4)  f     = XOR flip mask (bit3 = wire0)
//   bits [4:8)  ymask = wires with Y
//   bit  [8]    neg   = 1 iff nY == 2  (sign = -1; nY in {0,4} -> +1)
__constant__ unsigned short DESC41[41] = {
    0x000, 0x001, 0x002, 0x003, 0x133, 0x004, 0x005, 0x006, 0x007, 0x137,
    0x155, 0x157, 0x166, 0x167, 0x008, 0x009, 0x00A, 0x00B, 0x13B, 0x00C,
    0x00D, 0x00E, 0x00F, 0x13F, 0x15D, 0x15F, 0x16E, 0x16F, 0x199, 0x19B,
    0x1AA, 0x1AB, 0x19D, 0x19F, 0x1AE, 0x1AF, 0x1CC, 0x1CD, 0x1CE, 0x1CF,
    0x0FF
};

#define CNOTF(c_, t_)                                                         \
    {                                                                         \
        const int mc = 8 >> (c_), mt = 8 >> (t_);                             \
        _Pragma("unroll")                                                     \
        for (int k = 0; k < 16; ++k)                                          \
            if ((k & mc) && !(k & mt)) {                                      \
                float tmp = st[k]; st[k] = st[k | mt]; st[k | mt] = tmp;      \
            }                                                                 \
    }

#define SINCOS2(dc, ds, xa, xb)                                               \
    { float sa_, ca_, sb_, cb_;                                               \
      __sincosf(xa, &sa_, &ca_); __sincosf(xb, &sb_, &cb_);                   \
      dc = pk(ca_, cb_); ds = pk(sa_, sb_); }

__global__ void __launch_bounds__(256)
quantum_layer_kernel(const float4* __restrict__ inp,
                     const float*  __restrict__ params,
                     float4* __restrict__ out, int nquad, int B)
{
    __shared__ ulonglong2 sWA[41];   // packed {W0, W1} per term
    __shared__ ulonglong2 sWB[41];   // packed {W2, W3} per term

    const int tid  = threadIdx.x;
    const int wid  = tid >> 5;
    const int lane = tid & 31;

    // ================= Prologue: weights via register-resident U + shuffles.
    {
        float pc[8], ps[8];
#pragma unroll
        for (int g = 0; g < 8; ++g)
            __sincosf(0.5f * __ldg(&params[g]), &ps[g], &pc[g]);

        const int col = lane & 15;       // lane (l&15) holds U column (l&15)
        float st[16];
#pragma unroll
        for (int i = 0; i < 16; ++i) st[i] = (i == col) ? 1.0f : 0.0f;

        CNOTF(0, 1); CNOTF(1, 2); CNOTF(2, 3);
#pragma unroll
        for (int layer = 0; layer < 2; ++layer) {
#pragma unroll
            for (int w = 0; w < 4; ++w) {
                const float c = pc[layer * 4 + w], s = ps[layer * 4 + w];
                const int m = 8 >> w;
#pragma unroll
                for (int k = 0; k < 16; ++k)
                    if (!(k & m)) {
                        const int k1 = k | m;
                        float a0 = st[k], a1 = st[k1];
                        st[k]  = c * a0 - s * a1;
                        st[k1] = s * a0 + c * a1;
                    }
            }
            CNOTF(0, 1); CNOTF(1, 2); CNOTF(2, 3); CNOTF(3, 0);
        }

        // Warp wid handles tIdx = wid + 8*k, k = 0..5 (41 strings total).
#pragma unroll 3
        for (int k = 0; k < 6; ++k) {
            const int tIdx = wid + 8 * k;
            if (tIdx < 41) {
                const int desc  = DESC41[tIdx];
                const int f     = desc & 15;
                const int ymask = (desc >> 4) & 15;
                const float sgn = (desc & 0x100) ? -0.0625f : 0.0625f;

                // prod[m] = U[m, l] * U[m, l^f]  (f < 16: stays in half-warp)
                float prod[16];
#pragma unroll
                for (int m = 0; m < 16; ++m) {
                    float o = __shfl_xor_sync(0xffffffffu, st[m], f);
                    prod[m] = st[m] * o;
                }

                // S_j = sum_m prod[m] * (1 - 2*bit_{3-j}(m)) via butterflies
                float u[8], v[8];
#pragma unroll
                for (int a = 0; a < 8; ++a) {
                    u[a] = prod[2 * a] + prod[2 * a + 1];
                    v[a] = prod[2 * a] - prod[2 * a + 1];
                }
                float S3 = ((v[0] + v[1]) + (v[2] + v[3])) +
                           ((v[4] + v[5]) + (v[6] + v[7]));
                float a2[4], b2[4];
#pragma unroll
                for (int b = 0; b < 4; ++b) {
                    a2[b] = u[2 * b] + u[2 * b + 1];
                    b2[b] = u[2 * b] - u[2 * b + 1];
                }
                float S2 = (b2[0] + b2[1]) + (b2[2] + b2[3]);
                float A0 = a2[0] + a2[1], B0 = a2[0] - a2[1];
                float A1 = a2[2] + a2[3], B1 = a2[2] - a2[3];
                float S1 = B0 + B1;
                float S0 = A0 - A1;

                // v(l) parity sign, folded with sign/16.
                const float scale = (__popc(col & ymask) & 1) ? -sgn : sgn;
                float w0 = S0 * scale, w1 = S1 * scale;
                float w2 = S2 * scale, w3 = S3 * scale;

                // Sum over the 16 columns (xor offsets within half-warp).
#pragma unroll
                for (int off = 1; off < 16; off <<= 1) {
                    w0 += __shfl_xor_sync(0xffffffffu, w0, off);
                    w1 += __shfl_xor_sync(0xffffffffu, w1, off);
                    w2 += __shfl_xor_sync(0xffffffffu, w2, off);
                    w3 += __shfl_xor_sync(0xffffffffu, w3, off);
                }
                if (lane == 0) {
                    sWA[tIdx] = make_ulonglong2(pk(w0, w0), pk(w1, w1));
                    sWB[tIdx] = make_ulonglong2(pk(w2, w2), pk(w3, w3));
                }
            }
        }
    }
    __syncthreads();

    // ================= Main body: 4 batch items per thread (pairs P, Q).
    const int t = blockIdx.x * blockDim.x + tid;
    if (t >= nquad) return;

    const int i0 = 4 * t;
    const bool hB = (i0 + 1) < B, hC = (i0 + 2) < B, hD = (i0 + 3) < B;
    float4 inA = inp[i0];
    float4 inB = hB ? inp[i0 + 1] : inA;
    float4 inC = hC ? inp[i0 + 2] : inA;
    float4 inD = hD ? inp[i0 + 3] : inA;

    ull CP[4], SP[4], CQ[4], SQ[4];
    SINCOS2(CP[0], SP[0], inA.x, inB.x); SINCOS2(CQ[0], SQ[0], inC.x, inD.x);
    SINCOS2(CP[1], SP[1], inA.y, inB.y); SINCOS2(CQ[1], SQ[1], inC.y, inD.y);
    SINCOS2(CP[2], SP[2], inA.z, inB.z); SINCOS2(CQ[2], SQ[2], inC.z, inD.z);
    SINCOS2(CP[3], SP[3], inA.w, inB.w); SINCOS2(CQ[3], SQ[3], inC.w, inD.w);

    // Monomials over wires 0,1 for each lane-pair.
    ull mP01[9], mQ01[9];
    mP01[0] = F2_ONE;               mQ01[0] = F2_ONE;
    mP01[1] = CP[1];                mQ01[1] = CQ[1];
    mP01[2] = SP[1];                mQ01[2] = SQ[1];
    mP01[3] = CP[0];                mQ01[3] = CQ[0];
    mP01[6] = SP[0];                mQ01[6] = SQ[0];
    mP01[4] = f2mul(CP[0], CP[1]);  mQ01[4] = f2mul(CQ[0], CQ[1]);
    mP01[5] = f2mul(CP[0], SP[1]);  mQ01[5] = f2mul(CQ[0], SQ[1]);
    mP01[7] = f2mul(SP[0], CP[1]);  mQ01[7] = f2mul(SQ[0], CQ[1]);
    mP01[8] = f2mul(SP[0], SP[1]);  mQ01[8] = f2mul(SQ[0], SQ[1]);

    ull oP0 = 0, oP1 = 0, oP2 = 0, oP3 = 0;
    ull oQ0 = 0, oQ1 = 0, oQ2 = 0, oQ3 = 0;
    int idx = 0;
#pragma unroll
    for (int t0 = 0; t0 < 3; ++t0)
#pragma unroll
    for (int t1 = 0; t1 < 3; ++t1) {
        const int p01 = t0 * 3 + t1;
#pragma unroll
        for (int t2 = 0; t2 < 3; ++t2) {
            ull preP, preQ;
            bool preOne = false;
            if (t2 == 0) {
                preP = mP01[p01]; preQ = mQ01[p01]; preOne = (p01 == 0);
            } else if (p01 == 0) {
                preP = (t2 == 1) ? CP[2] : SP[2];
                preQ = (t2 == 1) ? CQ[2] : SQ[2];
            } else {
                preP = f2mul(mP01[p01], (t2 == 1) ? CP[2] : SP[2]);
                preQ = f2mul(mQ01[p01], (t2 == 1) ? CQ[2] : SQ[2]);
            }
#pragma unroll
            for (int t3 = 0; t3 < 3; ++t3) {
                const int ny = (t0 == 2) + (t1 == 2) + (t2 == 2) + (t3 == 2);
                if (ny & 1) continue;   // odd-Y strings have zero weight
                ull mP, mQ;
                if (t3 == 0) {
                    mP = preP; mQ = preQ;
                } else if (preOne) {
                    mP = (t3 == 1) ? CP[3] : SP[3];
                    mQ = (t3 == 1) ? CQ[3] : SQ[3];
                } else {
                    mP = f2mul(preP, (t3 == 1) ? CP[3] : SP[3]);
                    mQ = f2mul(preQ, (t3 == 1) ? CQ[3] : SQ[3]);
                }
                // 2x LDS.128 per term, reused by both lane-pairs.
                ulonglong2 wA = sWA[idx];   // {W0, W1}
                ulonglong2 wB = sWB[idx];   // {W2, W3}
                oP0 = f2fma(mP, wA.x, oP0);  oQ0 = f2fma(mQ, wA.x, oQ0);
                oP1 = f2fma(mP, wA.y, oP1);  oQ1 = f2fma(mQ, wA.y, oQ1);
                oP2 = f2fma(mP, wB.x, oP2);  oQ2 = f2fma(mQ, wB.x, oQ2);
                oP3 = f2fma(mP, wB.y, oP3);  oQ3 = f2fma(mQ, wB.y, oQ3);
                ++idx;
            }
        }
    }

    float a0, b0, a1, b1, a2, b2, a3, b3;
    upk(oP0, a0, b0); upk(oP1, a1, b1); upk(oP2, a2, b2); upk(oP3, a3, b3);
    out[i0] = make_float4(a0, a1, a2, a3);
    if (hB) out[i0 + 1] = make_float4(b0, b1, b2, b3);
    upk(oQ0, a0, b0); upk(oQ1, a1, b1); upk(oQ2, a2, b2); upk(oQ3, a3, b3);
    if (hC) out[i0 + 2] = make_float4(a0, a1, a2, a3);
    if (hD) out[i0 + 3] = make_float4(b0, b1, b2, b3);
}

extern "C" void kernel_launch(void* const* d_in, const int* in_sizes, int n_in,
                              void* d_out, int out_size)
{
    const float* inputs = (const float*)d_in[0];   // (B, 4) float32
    const float* params = (const float*)d_in[1];   // (2, 4) float32
    float* outp = (float*)d_out;                   // (B, 4) float32

    int B = in_sizes[0] / 4;
    int nquad = (B + 3) / 4;
    int threads = 256;
    int blocks = (nquad + threads - 1) / threads;

    quantum_layer_kernel<<<blocks, threads>>>((const float4*)inputs, params,
                                              (float4*)outp, nquad, B);
}

// round 17
// speedup vs baseline: 1.9518x; 1.2771x over previous
#include <cuda_runtime.h>

// QuantumLayer via Pauli-transfer closed form — single fused kernel.
//
// o_j = sum over the 41 even-Y Pauli strings t in {I,X,Y}^4 of
//       W_j[t] * prod_w (1 | cos th_w | sin th_w).
//
// Prologue (per block): warps simulate the fixed real orthogonal operator U
// (params-only) with lane (l&15) holding column (l&15) in registers, then
// compute weight quadruples via warp shuffles. The two half-warps process
// TWO DIFFERENT strings simultaneously (all shuffles stay within a half:
// f < 16, reduction offsets 1/2/4/8), halving prologue iterations. Each
// block also processes TWO contiguous 256-quad tiles, halving the number of
// prologue executions chip-wide. (R15 measured the prologue as aggregate
// issue-slot work ~6-8us across 1024 blocks; these two changes cut it ~4x.)
//
// Main body: 4 batch items per thread as two f32x2 lane-pairs; weight pairs
// packed as ulonglong2 -> 2x LDS.128 broadcast per term. Block-ordered
// contiguous tiles (grid-stride regressed memory 2.5x in R13).

typedef unsigned long long ull;

__device__ __forceinline__ ull pk(float a, float b) {
    ull r; asm("mov.b64 %0, {%1, %2};" : "=l"(r) : "f"(a), "f"(b)); return r;
}
__device__ __forceinline__ void upk(ull v, float& a, float& b) {
    asm("mov.b64 {%0, %1}, %2;" : "=f"(a), "=f"(b) : "l"(v));
}
__device__ __forceinline__ ull f2mul(ull a, ull b) {
    ull r; asm("mul.rn.f32x2 %0, %1, %2;" : "=l"(r) : "l"(a), "l"(b)); return r;
}
__device__ __forceinline__ ull f2fma(ull a, ull b, ull c) {
    ull r; asm("fma.rn.f32x2 %0, %1, %2, %3;" : "=l"(r) : "l"(a), "l"(b), "l"(c)); return r;
}

#define F2_ONE 0x3F8000003F800000ULL   // (1.0f, 1.0f)

// Packed descriptors for the 41 even-Y Pauli strings, ascending enc order
// (== main loop idx order). Validated on HW in R13/R15 (rel_err 7.3e-6):
//   bits [0:4)  f     = XOR flip mask (bit3 = wire0)
//   bits [4:8)  ymask = wires with Y
//   bit  [8]    neg   = 1 iff nY == 2  (sign = -1; nY in {0,4} -> +1)
// Padded to 48 with zeros (slots 41-47 computed but never written).
__constant__ unsigned short DESC48[48] = {
    0x000, 0x001, 0x002, 0x003, 0x133, 0x004, 0x005, 0x006, 0x007, 0x137,
    0x155, 0x157, 0x166, 0x167, 0x008, 0x009, 0x00A, 0x00B, 0x13B, 0x00C,
    0x00D, 0x00E, 0x00F, 0x13F, 0x15D, 0x15F, 0x16E, 0x16F, 0x199, 0x19B,
    0x1AA, 0x1AB, 0x19D, 0x19F, 0x1AE, 0x1AF, 0x1CC, 0x1CD, 0x1CE, 0x1CF,
    0x0FF, 0x000, 0x000, 0x000, 0x000, 0x000, 0x000, 0x000
};

#define CNOTF(c_, t_)                                                         \
    {                                                                         \
        const int mc = 8 >> (c_), mt = 8 >> (t_);                             \
        _Pragma("unroll")                                                     \
        for (int k = 0; k < 16; ++k)                                          \
            if ((k & mc) && !(k & mt)) {                                      \
                float tmp = st[k]; st[k] = st[k | mt]; st[k | mt] = tmp;      \
            }                                                                 \
    }

#define SINCOS2(dc, ds, xa, xb)                                               \
    { float sa_, ca_, sb_, cb_;                                               \
      __sincosf(xa, &sa_, &ca_); __sincosf(xb, &sb_, &cb_);                   \
      dc = pk(ca_, cb_); ds = pk(sa_, sb_); }

__global__ void __launch_bounds__(256, 3)
quantum_layer_kernel(const float4* __restrict__ inp,
                     const float*  __restrict__ params,
                     float4* __restrict__ out, int nquad, int B)
{
    __shared__ ulonglong2 sWA[41];   // packed {W0, W1} per term
    __shared__ ulonglong2 sWB[41];   // packed {W2, W3} per term

    const int tid  = threadIdx.x;
    const int wid  = tid >> 5;
    const int lane = tid & 31;

    // ===== Prologue: weights via register-resident U + half-warp-paired
    //       shuffles. Lanes 0-15 process string (wid+16k), lanes 16-31
    //       process string (wid+8+16k), k = 0..2 — covers all 41.
    {
        float pc[8], ps[8];
#pragma unroll
        for (int g = 0; g < 8; ++g)
            __sincosf(0.5f * __ldg(&params[g]), &ps[g], &pc[g]);

        const int col = lane & 15;       // lane (l&15) holds U column (l&15)
        const int hiHalf = lane >> 4;    // 0: lanes 0-15, 1: lanes 16-31
        float st[16];
#pragma unroll
        for (int i = 0; i < 16; ++i) st[i] = (i == col) ? 1.0f : 0.0f;

        CNOTF(0, 1); CNOTF(1, 2); CNOTF(2, 3);
#pragma unroll
        for (int layer = 0; layer < 2; ++layer) {
#pragma unroll
            for (int w = 0; w < 4; ++w) {
                const float c = pc[layer * 4 + w], s = ps[layer * 4 + w];
                const int m = 8 >> w;
#pragma unroll
                for (int k = 0; k < 16; ++k)
                    if (!(k & m)) {
                        const int k1 = k | m;
                        float a0 = st[k], a1 = st[k1];
                        st[k]  = c * a0 - s * a1;
                        st[k1] = s * a0 + c * a1;
                    }
            }
            CNOTF(0, 1); CNOTF(1, 2); CNOTF(2, 3); CNOTF(3, 0);
        }

#pragma unroll
        for (int k = 0; k < 3; ++k) {
            // Per-lane string index: two strings per warp-iteration.
            const int tIdx  = wid + (hiHalf << 3) + (k << 4);
            const int desc  = DESC48[tIdx];
            const int f     = desc & 15;           // f < 16: stays in half
            const int ymask = (desc >> 4) & 15;
            const float sgn = (desc & 0x100) ? -0.0625f : 0.0625f;

            // prod[m] = U[m, l] * U[m, l^f]
            float prod[16];
#pragma unroll
            for (int m = 0; m < 16; ++m) {
                float o = __shfl_xor_sync(0xffffffffu, st[m], f);
                prod[m] = st[m] * o;
            }

            // S_j = sum_m prod[m] * (1 - 2*bit_{3-j}(m)) via butterflies
            float u[8], v[8];
#pragma unroll
            for (int a = 0; a < 8; ++a) {
                u[a] = prod[2 * a] + prod[2 * a + 1];
                v[a] = prod[2 * a] - prod[2 * a + 1];
            }
            float S3 = ((v[0] + v[1]) + (v[2] + v[3])) +
                       ((v[4] + v[5]) + (v[6] + v[7]));
            float a2[4], b2[4];
#pragma unroll
            for (int b = 0; b < 4; ++b) {
                a2[b] = u[2 * b] + u[2 * b + 1];
                b2[b] = u[2 * b] - u[2 * b + 1];
            }
            float S2 = (b2[0] + b2[1]) + (b2[2] + b2[3]);
            float A0 = a2[0] + a2[1], B0 = a2[0] - a2[1];
            float A1 = a2[2] + a2[3], B1 = a2[2] - a2[3];
            float S1 = B0 + B1;
            float S0 = A0 - A1;

            // v(l) parity sign, folded with sign/16.
            const float scale = (__popc(col & ymask) & 1) ? -sgn : sgn;
            float w0 = S0 * scale, w1 = S1 * scale;
            float w2 = S2 * scale, w3 = S3 * scale;

            // Sum over the 16 columns of this half (offsets 1,2,4,8).
#pragma unroll
            for (int off = 1; off < 16; off <<= 1) {
                w0 += __shfl_xor_sync(0xffffffffu, w0, off);
                w1 += __shfl_xor_sync(0xffffffffu, w1, off);
                w2 += __shfl_xor_sync(0xffffffffu, w2, off);
                w3 += __shfl_xor_sync(0xffffffffu, w3, off);
            }
            if (col == 0 && tIdx < 41) {   // lane 0 and lane 16 write
                sWA[tIdx] = make_ulonglong2(pk(w0, w0), pk(w1, w1));
                sWB[tIdx] = make_ulonglong2(pk(w2, w2), pk(w3, w3));
            }
        }
    }
    __syncthreads();

    // ===== Main body: two contiguous 256-quad tiles per block.
    auto process_quad = [&](int t) {
        const int i0 = 4 * t;
        const bool hB = (i0 + 1) < B, hC = (i0 + 2) < B, hD = (i0 + 3) < B;
        float4 inA = inp[i0];
        float4 inB = hB ? inp[i0 + 1] : inA;
        float4 inC = hC ? inp[i0 + 2] : inA;
        float4 inD = hD ? inp[i0 + 3] : inA;

        ull CP[4], SP[4], CQ[4], SQ[4];
        SINCOS2(CP[0], SP[0], inA.x, inB.x); SINCOS2(CQ[0], SQ[0], inC.x, inD.x);
        SINCOS2(CP[1], SP[1], inA.y, inB.y); SINCOS2(CQ[1], SQ[1], inC.y, inD.y);
        SINCOS2(CP[2], SP[2], inA.z, inB.z); SINCOS2(CQ[2], SQ[2], inC.z, inD.z);
        SINCOS2(CP[3], SP[3], inA.w, inB.w); SINCOS2(CQ[3], SQ[3], inC.w, inD.w);

        // Monomials over wires 0,1 for each lane-pair.
        ull mP01[9], mQ01[9];
        mP01[0] = F2_ONE;               mQ01[0] = F2_ONE;
        mP01[1] = CP[1];                mQ01[1] = CQ[1];
        mP01[2] = SP[1];                mQ01[2] = SQ[1];
        mP01[3] = CP[0];                mQ01[3] = CQ[0];
        mP01[6] = SP[0];                mQ01[6] = SQ[0];
        mP01[4] = f2mul(CP[0], CP[1]);  mQ01[4] = f2mul(CQ[0], CQ[1]);
        mP01[5] = f2mul(CP[0], SP[1]);  mQ01[5] = f2mul(CQ[0], SQ[1]);
        mP01[7] = f2mul(SP[0], CP[1]);  mQ01[7] = f2mul(SQ[0], CQ[1]);
        mP01[8] = f2mul(SP[0], SP[1]);  mQ01[8] = f2mul(SQ[0], SQ[1]);

        ull oP0 = 0, oP1 = 0, oP2 = 0, oP3 = 0;
        ull oQ0 = 0, oQ1 = 0, oQ2 = 0, oQ3 = 0;
        int idx = 0;
#pragma unroll
        for (int t0 = 0; t0 < 3; ++t0)
#pragma unroll
        for (int t1 = 0; t1 < 3; ++t1) {
            const int p01 = t0 * 3 + t1;
#pragma unroll
            for (int t2 = 0; t2 < 3; ++t2) {
                ull preP, preQ;
                bool preOne = false;
                if (t2 == 0) {
                    preP = mP01[p01]; preQ = mQ01[p01]; preOne = (p01 == 0);
                } else if (p01 == 0) {
                    preP = (t2 == 1) ? CP[2] : SP[2];
                    preQ = (t2 == 1) ? CQ[2] : SQ[2];
                } else {
                    preP = f2mul(mP01[p01], (t2 == 1) ? CP[2] : SP[2]);
                    preQ = f2mul(mQ01[p01], (t2 == 1) ? CQ[2] : SQ[2]);
                }
#pragma unroll
                for (int t3 = 0; t3 < 3; ++t3) {
                    const int ny = (t0 == 2) + (t1 == 2) + (t2 == 2) + (t3 == 2);
                    if (ny & 1) continue;   // odd-Y strings have zero weight
                    ull mP, mQ;
                    if (t3 == 0) {
                        mP = preP; mQ = preQ;
                    } else if (preOne) {
                        mP = (t3 == 1) ? CP[3] : SP[3];
                        mQ = (t3 == 1) ? CQ[3] : SQ[3];
                    } else {
                        mP = f2mul(preP, (t3 == 1) ? CP[3] : SP[3]);
                        mQ = f2mul(preQ, (t3 == 1) ? CQ[3] : SQ[3]);
                    }
                    // 2x LDS.128 per term, reused by both lane-pairs.
                    ulonglong2 wA = sWA[idx];   // {W0, W1}
                    ulonglong2 wB = sWB[idx];   // {W2, W3}
                    oP0 = f2fma(mP, wA.x, oP0);  oQ0 = f2fma(mQ, wA.x, oQ0);
                    oP1 = f2fma(mP, wA.y, oP1);  oQ1 = f2fma(mQ, wA.y, oQ1);
                    oP2 = f2fma(mP, wB.x, oP2);  oQ2 = f2fma(mQ, wB.x, oQ2);
                    oP3 = f2fma(mP, wB.y, oP3);  oQ3 = f2fma(mQ, wB.y, oQ3);
                    ++idx;
                }
            }
        }

        float a0, b0, a1, b1, a2, b2, a3, b3;
        upk(oP0, a0, b0); upk(oP1, a1, b1); upk(oP2, a2, b2); upk(oP3, a3, b3);
        out[i0] = make_float4(a0, a1, a2, a3);
        if (hB) out[i0 + 1] = make_float4(b0, b1, b2, b3);
        upk(oQ0, a0, b0); upk(oQ1, a1, b1); upk(oQ2, a2, b2); upk(oQ3, a3, b3);
        if (hC) out[i0 + 2] = make_float4(a0, a1, a2, a3);
        if (hD) out[i0 + 3] = make_float4(b0, b1, b2, b3);
    };

    const int base = blockIdx.x * 512 + tid;   // two tiles: base, base+256
    if (base < nquad)       process_quad(base);
    if (base + 256 < nquad) process_quad(base + 256);
}

extern "C" void kernel_launch(void* const* d_in, const int* in_sizes, int n_in,
                              void* d_out, int out_size)
{
    const float* inputs = (const float*)d_in[0];   // (B, 4) float32
    const float* params = (const float*)d_in[1];   // (2, 4) float32
    float* outp = (float*)d_out;                   // (B, 4) float32

    int B = in_sizes[0] / 4;
    int nquad = (B + 3) / 4;
    int threads = 256;
    int blocks = (nquad + 511) / 512;              // 2 tiles of 256 per block

    quantum_layer_kernel<<<blocks, threads>>>((const float4*)inputs, params,
                                              (float4*)outp, nquad, B);
}